// round 1
// baseline (speedup 1.0000x reference)
#include <cuda_runtime.h>

#define HID   2048
#define NH    16
#define HD    128
#define QKV_N 2304
#define BB    2
#define SS    2048
#define MTOT  4096

// Scratch (no allocs allowed)
__device__ float g_qkv[(size_t)MTOT * QKV_N];   // 37.7 MB
__device__ float g_att[(size_t)MTOT * HID];     // 33.6 MB

// ---------------------------------------------------------------------------
// SGEMM with bias: C[M,N] = A[M,K] @ B[K,N] + bias[N]
// BM=BN=128, BK=16, 256 threads, 8x8 microtile. All dims divide evenly.
// ---------------------------------------------------------------------------
__global__ __launch_bounds__(256) void sgemm_bias(
    const float* __restrict__ A, const float* __restrict__ Bm,
    const float* __restrict__ bias, float* __restrict__ C,
    int M, int N, int K)
{
    __shared__ float As[16 * 132];   // transposed: As[k][m], padded
    __shared__ float Bs[16 * 128];   // Bs[k][n]

    const int bx = blockIdx.x;       // N tile
    const int by = blockIdx.y;       // M tile
    const int tid = threadIdx.x;
    const int tx = tid % 16;
    const int ty = tid / 16;

    const float* Ab = A + (size_t)by * 128 * K;
    const float* Bb = Bm + (size_t)bx * 128;

    float acc[8][8];
#pragma unroll
    for (int i = 0; i < 8; i++)
#pragma unroll
        for (int j = 0; j < 8; j++) acc[i][j] = 0.f;

    for (int k0 = 0; k0 < K; k0 += 16) {
#pragma unroll
        for (int it = 0; it < 2; it++) {
            int idx = tid + it * 256;
            // A tile 128x16: 512 float4
            int ar = idx >> 2;
            int ac = (idx & 3) * 4;
            float4 av = *(const float4*)(Ab + (size_t)ar * K + k0 + ac);
            As[(ac + 0) * 132 + ar] = av.x;
            As[(ac + 1) * 132 + ar] = av.y;
            As[(ac + 2) * 132 + ar] = av.z;
            As[(ac + 3) * 132 + ar] = av.w;
            // B tile 16x128: 512 float4
            int br = idx >> 5;
            int bc = (idx & 31) * 4;
            float4 bv = *(const float4*)(Bb + (size_t)(k0 + br) * N + bc);
            *(float4*)&Bs[br * 128 + bc] = bv;
        }
        __syncthreads();

#pragma unroll
        for (int k = 0; k < 16; k++) {
            float a[8], b[8];
            float4 a0 = *(const float4*)&As[k * 132 + ty * 8];
            float4 a1 = *(const float4*)&As[k * 132 + ty * 8 + 4];
            float4 b0 = *(const float4*)&Bs[k * 128 + tx * 8];
            float4 b1 = *(const float4*)&Bs[k * 128 + tx * 8 + 4];
            a[0]=a0.x; a[1]=a0.y; a[2]=a0.z; a[3]=a0.w;
            a[4]=a1.x; a[5]=a1.y; a[6]=a1.z; a[7]=a1.w;
            b[0]=b0.x; b[1]=b0.y; b[2]=b0.z; b[3]=b0.w;
            b[4]=b1.x; b[5]=b1.y; b[6]=b1.z; b[7]=b1.w;
#pragma unroll
            for (int i = 0; i < 8; i++)
#pragma unroll
                for (int j = 0; j < 8; j++)
                    acc[i][j] += a[i] * b[j];
        }
        __syncthreads();
    }

    const int col = bx * 128 + tx * 8;
    float4 bi0 = *(const float4*)(bias + col);
    float4 bi1 = *(const float4*)(bias + col + 4);
#pragma unroll
    for (int i = 0; i < 8; i++) {
        int row = by * 128 + ty * 8 + i;
        float4 o0, o1;
        o0.x = acc[i][0] + bi0.x; o0.y = acc[i][1] + bi0.y;
        o0.z = acc[i][2] + bi0.z; o0.w = acc[i][3] + bi0.w;
        o1.x = acc[i][4] + bi1.x; o1.y = acc[i][5] + bi1.y;
        o1.z = acc[i][6] + bi1.z; o1.w = acc[i][7] + bi1.w;
        *(float4*)(C + (size_t)row * N + col)     = o0;
        *(float4*)(C + (size_t)row * N + col + 4) = o1;
    }
}

// ---------------------------------------------------------------------------
// MQA flash attention (causal), fp32.
// Grid: (S/64, NH, B). Block: 256 threads.
// Q tile 64x128, KV tiles 64x128 from g_qkv (K at col 2048, V at col 2176).
// Phase A: scores + online softmax -> Ps (4 lanes per row).
// Phase B: register-tiled P @ V  (thread owns 4 rows x 8 dims).
// ---------------------------------------------------------------------------
#define BQ  64
#define BKV 64
#define QP  132
#define KP  132
#define PP  65

__global__ __launch_bounds__(256, 1) void mqa_kernel(
    const float* __restrict__ qkv, float* __restrict__ out)
{
    extern __shared__ float sm[];
    float* Qs = sm;                      // 64*132
    float* Ks = Qs + BQ * QP;            // 64*132
    float* Vs = Ks + BKV * KP;           // 64*128
    float* Ps = Vs + BKV * HD;           // 64*65
    float* Cs = Ps + BQ * PP;            // 64 correction factors
    float* Ls = Cs + BQ;                 // 64 row sums

    const int qt  = blockIdx.x;
    const int h   = blockIdx.y;
    const int b   = blockIdx.z;
    const int tid = threadIdx.x;
    const int q0  = qt * BQ;
    const float scale = 0.088388347648318447f; // 1/sqrt(128)

    // load Q tile
    for (int i = tid; i < BQ * HD / 4; i += 256) {
        int r  = i >> 5;
        int c4 = (i & 31) * 4;
        float4 v = *(const float4*)(qkv + (size_t)(b * SS + q0 + r) * QKV_N + h * HD + c4);
        float* dst = Qs + r * QP + c4;
        dst[0] = v.x; dst[1] = v.y; dst[2] = v.z; dst[3] = v.w;
    }

    // phase A state: 4 lanes per row
    const int lane4 = tid & 3;
    const int rA    = tid >> 2;          // 0..63
    float m_i = -1e30f, l_i = 0.f;

    // phase B ownership: rows ty*4..+3, cols tx*8..+7
    const int tx = tid % 16;
    const int ty = tid / 16;
    const int row0 = ty * 4;
    float acc[4][8];
#pragma unroll
    for (int i = 0; i < 4; i++)
#pragma unroll
        for (int j = 0; j < 8; j++) acc[i][j] = 0.f;

    for (int j = 0; j <= qt; j++) {
        __syncthreads();  // prev phase B done with Ks/Vs/Ps
        const int k0 = j * BKV;

        // load K and V tiles
        for (int i = tid; i < BKV * HD / 4; i += 256) {
            int r  = i >> 5;
            int c4 = (i & 31) * 4;
            const float* base = qkv + (size_t)(b * SS + k0 + r) * QKV_N;
            float4 kk = *(const float4*)(base + HID + c4);
            float* dk = Ks + r * KP + c4;
            dk[0] = kk.x; dk[1] = kk.y; dk[2] = kk.z; dk[3] = kk.w;
            float4 vv = *(const float4*)(base + HID + HD + c4);
            *(float4*)(Vs + r * HD + c4) = vv;
        }
        __syncthreads();

        // -------- phase A: scores + online softmax --------
        {
            float s[16];
#pragma unroll
            for (int ci = 0; ci < 16; ci++) s[ci] = 0.f;
            const float* Qrow = Qs + rA * QP;
#pragma unroll 4
            for (int k4 = 0; k4 < 32; k4++) {
                float4 q = *(const float4*)(Qrow + 4 * k4);
#pragma unroll
                for (int ci = 0; ci < 16; ci++) {
                    int cc = lane4 + 4 * ci;
                    float4 kk = *(const float4*)(Ks + cc * KP + 4 * k4);
                    s[ci] += q.x * kk.x + q.y * kk.y + q.z * kk.z + q.w * kk.w;
                }
            }
            const bool diag = (j == qt);
#pragma unroll
            for (int ci = 0; ci < 16; ci++) {
                int cc = lane4 + 4 * ci;
                float v = s[ci] * scale;
                if (diag && (k0 + cc > q0 + rA)) v = -1e30f;
                s[ci] = v;
            }
            float mloc = s[0];
#pragma unroll
            for (int ci = 1; ci < 16; ci++) mloc = fmaxf(mloc, s[ci]);
            mloc = fmaxf(mloc, __shfl_xor_sync(0xffffffffu, mloc, 1));
            mloc = fmaxf(mloc, __shfl_xor_sync(0xffffffffu, mloc, 2));
            float mnew = fmaxf(m_i, mloc);
            float corr = __expf(m_i - mnew);
            float psum = 0.f;
#pragma unroll
            for (int ci = 0; ci < 16; ci++) {
                float p = __expf(s[ci] - mnew);
                Ps[rA * PP + lane4 + 4 * ci] = p;
                psum += p;
            }
            psum += __shfl_xor_sync(0xffffffffu, psum, 1);
            psum += __shfl_xor_sync(0xffffffffu, psum, 2);
            l_i = l_i * corr + psum;
            m_i = mnew;
            if (lane4 == 0) { Cs[rA] = corr; Ls[rA] = l_i; }
        }
        __syncthreads();

        // -------- phase B: acc = acc*corr + P @ V --------
        {
            float cr[4];
#pragma unroll
            for (int i = 0; i < 4; i++) cr[i] = Cs[row0 + i];
#pragma unroll
            for (int i = 0; i < 4; i++)
#pragma unroll
                for (int jj = 0; jj < 8; jj++) acc[i][jj] *= cr[i];

#pragma unroll 4
            for (int c = 0; c < BKV; c++) {
                float p0 = Ps[(row0 + 0) * PP + c];
                float p1 = Ps[(row0 + 1) * PP + c];
                float p2 = Ps[(row0 + 2) * PP + c];
                float p3 = Ps[(row0 + 3) * PP + c];
                float4 v0 = *(const float4*)(Vs + c * HD + tx * 8);
                float4 v1 = *(const float4*)(Vs + c * HD + tx * 8 + 4);
                float vv[8] = {v0.x, v0.y, v0.z, v0.w, v1.x, v1.y, v1.z, v1.w};
#pragma unroll
                for (int jj = 0; jj < 8; jj++) {
                    acc[0][jj] += p0 * vv[jj];
                    acc[1][jj] += p1 * vv[jj];
                    acc[2][jj] += p2 * vv[jj];
                    acc[3][jj] += p3 * vv[jj];
                }
            }
        }
    }

    // epilogue: divide by row sums, write attn output (Ls final after last A, synced)
#pragma unroll
    for (int i = 0; i < 4; i++) {
        float linv = 1.f / Ls[row0 + i];
        int qg = q0 + row0 + i;
        float4 o0, o1;
        o0.x = acc[i][0] * linv; o0.y = acc[i][1] * linv;
        o0.z = acc[i][2] * linv; o0.w = acc[i][3] * linv;
        o1.x = acc[i][4] * linv; o1.y = acc[i][5] * linv;
        o1.z = acc[i][6] * linv; o1.w = acc[i][7] * linv;
        float* dst = out + (size_t)(b * SS + qg) * HID + h * HD + tx * 8;
        *(float4*)dst       = o0;
        *(float4*)(dst + 4) = o1;
    }
}

// ---------------------------------------------------------------------------
// kernel_launch
// inputs: 0 hidden_states [2,2048,2048] f32, 1 attention_mask (ignored; exact
// causal), 2 c_attn_w [2048,2304], 3 c_attn_b [2304], 4 c_proj_w [2048,2048],
// 5 c_proj_b [2048]. Output: [2,2048,2048] f32.
// ---------------------------------------------------------------------------
extern "C" void kernel_launch(void* const* d_in, const int* in_sizes, int n_in,
                              void* d_out, int out_size)
{
    const float* hidden = (const float*)d_in[0];
    const float* w1     = (const float*)d_in[2];
    const float* b1     = (const float*)d_in[3];
    const float* w2     = (const float*)d_in[4];
    const float* b2     = (const float*)d_in[5];
    float* out          = (float*)d_out;

    float *qkv, *att;
    cudaGetSymbolAddress((void**)&qkv, g_qkv);
    cudaGetSymbolAddress((void**)&att, g_att);

    // QKV projection
    dim3 g1(QKV_N / 128, MTOT / 128);
    sgemm_bias<<<g1, 256>>>(hidden, w1, b1, qkv, MTOT, QKV_N, HID);

    // attention
    size_t smem = (size_t)(BQ * QP + BKV * KP + BKV * HD + BQ * PP + 2 * BQ) * sizeof(float);
    cudaFuncSetAttribute(mqa_kernel, cudaFuncAttributeMaxDynamicSharedMemorySize, (int)smem);
    mqa_kernel<<<dim3(SS / BQ, NH, BB), 256, smem>>>(qkv, att);

    // output projection
    dim3 g2(HID / 128, MTOT / 128);
    sgemm_bias<<<g2, 256>>>(att, w2, b2, out, MTOT, HID, HID);
}